// round 9
// baseline (speedup 1.0000x reference)
#include <cuda_runtime.h>

// Problem constants (LatentCoulombLongRange: N=8192, F=128, H=64, B=8)
#define MAXN 8192
#define FDIM 128
#define HDIM 64
#define MAXB 64
#define TILE 1024          // pair-kernel j-chunk staged in SMEM

// Scratch (allocation-free rule: __device__ globals).
// NOTE: no cross-replay mutable state — everything rewritten each replay.
__device__ float d_qraw[MAXN];
__device__ int   d_gstart[MAXB];
__device__ int   d_gend[MAXB];

// ---- raw single-MUFU intrinsics (avoid non-fast-math slow paths) ----------
__device__ __forceinline__ float fast_rsqrt(float x) {
    float r; asm("rsqrt.approx.ftz.f32 %0, %1;" : "=f"(r) : "f"(x)); return r;
}
__device__ __forceinline__ float fast_ex2(float x) {
    float r; asm("ex2.approx.ftz.f32 %0, %1;" : "=f"(r) : "f"(x)); return r;
}
__device__ __forceinline__ float fast_rcp(float x) {
    float r; asm("rcp.approx.ftz.f32 %0, %1;" : "=f"(r) : "f"(x)); return r;
}

#define LOG2E 1.44269504088896f

__device__ __forceinline__ float silu_f(float v) {
    return v * fast_rcp(1.0f + fast_ex2(-LOG2E * v));
}

// ---------------------------------------------------------------------------
// K1: charge-head MLP as a register-tiled GEMM.
//     Block = 256 threads, tile = 64 atoms x 64 h, K=128 in 2 chunks of 64.
//     Thread (tx = t&15, ty = t>>4) owns a 4x4 output tile:
//     atoms m0..m0+3 (m0 = 4*ty), h cols h0..h0+3 (h0 = 4*tx).
//     Per k-step: 1 LDS.128 (x frag) + 1 LDS.128 (w frag) -> 16 FFMA.
//     Epilogue: SiLU + W2 dot, reduce over tx (16 threads) via shfl_xor.
// ---------------------------------------------------------------------------
__global__ __launch_bounds__(256)
void mlp_kernel(const float* __restrict__ x,
                const float* __restrict__ W1,
                const float* __restrict__ b1,
                const float* __restrict__ W2,
                const float* __restrict__ b2,
                const int* __restrict__ batch,
                int n) {
    __shared__ float xs[64][68];   // [k_local][atom], padded (68 = 17*4 words, 16B-aligned rows)
    __shared__ float ws[64][64];   // [k_local][h]

    int t  = threadIdx.x;
    int tx = t & 15, ty = t >> 4;
    int base = blockIdx.x * 64;
    int m0 = ty * 4, h0 = tx * 4;

    float acc[4][4] = {{0.f,0.f,0.f,0.f},{0.f,0.f,0.f,0.f},
                       {0.f,0.f,0.f,0.f},{0.f,0.f,0.f,0.f}};

    const float4* xv4  = (const float4*)x;    // 32 float4 per atom row
    const float4* w1v4 = (const float4*)W1;   // 16 float4 per f row

    for (int kc = 0; kc < FDIM; kc += 64) {
        // stage x chunk transposed: atoms base..base+63, f in [kc, kc+64)
        {
            int a  = t >> 2;                   // 0..63
            int u0 = t & 3;
            int arow = min(base + a, n - 1);   // clamp (n % 64 == 0 normally)
#pragma unroll
            for (int it = 0; it < 4; it++) {
                int u = u0 + it * 4;           // float4 unit 0..15 within chunk
                float4 v = xv4[arow * (FDIM / 4) + (kc >> 2) + u];
                xs[4 * u + 0][a] = v.x;
                xs[4 * u + 1][a] = v.y;
                xs[4 * u + 2][a] = v.z;
                xs[4 * u + 3][a] = v.w;
            }
        }
        // stage W1 chunk: rows kc..kc+63
        {
#pragma unroll
            for (int it = 0; it < 4; it++) {
                int idx = t + it * 256;        // 0..1023
                int kl = idx >> 4, c4 = idx & 15;
                *(float4*)&ws[kl][c4 * 4] = w1v4[(kc + kl) * (HDIM / 4) + c4];
            }
        }
        __syncthreads();

#pragma unroll 8
        for (int k = 0; k < 64; k++) {
            float4 xf = *(const float4*)&xs[k][m0];
            float4 wf = *(const float4*)&ws[k][h0];
            acc[0][0] = fmaf(xf.x, wf.x, acc[0][0]);
            acc[0][1] = fmaf(xf.x, wf.y, acc[0][1]);
            acc[0][2] = fmaf(xf.x, wf.z, acc[0][2]);
            acc[0][3] = fmaf(xf.x, wf.w, acc[0][3]);
            acc[1][0] = fmaf(xf.y, wf.x, acc[1][0]);
            acc[1][1] = fmaf(xf.y, wf.y, acc[1][1]);
            acc[1][2] = fmaf(xf.y, wf.z, acc[1][2]);
            acc[1][3] = fmaf(xf.y, wf.w, acc[1][3]);
            acc[2][0] = fmaf(xf.z, wf.x, acc[2][0]);
            acc[2][1] = fmaf(xf.z, wf.y, acc[2][1]);
            acc[2][2] = fmaf(xf.z, wf.z, acc[2][2]);
            acc[2][3] = fmaf(xf.z, wf.w, acc[2][3]);
            acc[3][0] = fmaf(xf.w, wf.x, acc[3][0]);
            acc[3][1] = fmaf(xf.w, wf.y, acc[3][1]);
            acc[3][2] = fmaf(xf.w, wf.z, acc[3][2]);
            acc[3][3] = fmaf(xf.w, wf.w, acc[3][3]);
        }
        __syncthreads();
    }

    // epilogue: SiLU + W2 contraction over this thread's 4 h-cols
    float4 b1v = ((const float4*)b1)[tx];
    float4 w2v = ((const float4*)W2)[tx];
    float part[4];
#pragma unroll
    for (int a = 0; a < 4; a++) {
        float p;
        p = silu_f(acc[a][0] + b1v.x) * w2v.x;
        p = fmaf(silu_f(acc[a][1] + b1v.y), w2v.y, p);
        p = fmaf(silu_f(acc[a][2] + b1v.z), w2v.z, p);
        p = fmaf(silu_f(acc[a][3] + b1v.w), w2v.w, p);
        part[a] = p;
    }
    // reduce over tx (16 threads, xor offsets < 16 stay in group)
#pragma unroll
    for (int off = 1; off < 16; off <<= 1) {
#pragma unroll
        for (int a = 0; a < 4; a++)
            part[a] += __shfl_xor_sync(0xffffffffu, part[a], off);
    }

    if (tx == 0) {
        float bias = b2[0];
#pragma unroll
        for (int a = 0; a < 4; a++) {
            int i = base + m0 + a;
            if (i < n) {
                d_qraw[i] = part[a] + bias;
                int g = batch[i];
                // sorted-batch segment boundaries
                if (i == 0     || batch[i - 1] != g) d_gstart[g] = i;
                if (i == n - 1 || batch[i + 1] != g) d_gend[g]   = i + 1;
            }
        }
    }
}

// ---------------------------------------------------------------------------
// K2: fused neutralize + pack + screened Coulomb pair sum.
//     Block = 256 threads / 8 warps = 8 atoms. Prologue: block computes the
//     per-graph means it needs (run-length partial sums of d_qraw over
//     [jmin, jmax), smem atomics). Then j-chunks of {pos, qc} are staged as
//     float4 in SMEM and each warp accumulates over its graph's range.
//     Self-term included in the loop, subtracted with the IDENTICAL intrinsic
//     sequence so the approximation error cancels exactly.
// ---------------------------------------------------------------------------
__device__ __forceinline__ float pair_term(float4 pj, float4 pi,
                                           float soft2, float nscr_log2e,
                                           float& k_out) {
    float dx = pj.x - pi.x;
    float dy = pj.y - pi.y;
    float dz = pj.z - pi.z;
    float r2 = fmaf(dx, dx, fmaf(dy, dy, fmaf(dz, dz, soft2)));
    float rinv = fast_rsqrt(r2);
    float r = r2 * rinv;
    k_out = fast_ex2(nscr_log2e * r) * rinv;
    return pj.w;
}

__global__ __launch_bounds__(256)
void pair_kernel(const float* __restrict__ pos,
                 const int* __restrict__ batch,
                 const float* __restrict__ scr_p,
                 const float* __restrict__ soft_p,
                 float* __restrict__ out, int n) {
    __shared__ float4 sqp[TILE];       // staged {pos, centered q}
    __shared__ float  ssum[MAXB];
    __shared__ float  smeanv[MAXB];

    int t    = threadIdx.x;
    int warp = t >> 5, lane = t & 31;
    int i    = blockIdx.x * 8 + warp;

    // block j-range (sorted batch => contiguous superset of all 8 atoms' graphs)
    int first = blockIdx.x * 8;
    int last  = min(first + 7, n - 1);
    int jmin  = d_gstart[batch[first]];
    int jmax  = d_gend[batch[last]];

    if (t < MAXB) ssum[t] = 0.0f;
    __syncthreads();

    // per-thread contiguous run-length partial sums of qraw over [jmin, jmax)
    {
        int len = jmax - jmin;
        int per = (len + 255) >> 8;
        int a0 = jmin + t * per;
        int a1 = min(jmax, a0 + per);
        if (a0 < a1) {
            int cg = batch[a0];
            float s = 0.0f;
            for (int a = a0; a < a1; a++) {
                int g = batch[a];
                if (g != cg) { atomicAdd(&ssum[cg], s); s = 0.0f; cg = g; }
                s += d_qraw[a];
            }
            atomicAdd(&ssum[cg], s);
        }
    }
    __syncthreads();
    if (t < MAXB) {
        float c = (float)max(1, d_gend[t] - d_gstart[t]);
        smeanv[t] = ssum[t] / c;       // valid for graphs this block touches
    }
    __syncthreads();

    float scr   = *scr_p;
    float soft  = *soft_p;
    float soft2 = soft * soft;
    const float nl = -scr * LOG2E;

    bool active = (i < n);
    int gs = 0, ge = 0;
    float4 pi = make_float4(0.f, 0.f, 0.f, 0.f);
    if (active) {
        int g = batch[i];
        gs = d_gstart[g];
        ge = d_gend[g];
        pi = make_float4(pos[3 * i], pos[3 * i + 1], pos[3 * i + 2],
                         d_qraw[i] - smeanv[g]);
    }

    float acc = 0.0f;
    for (int c0 = jmin; c0 < jmax; c0 += TILE) {
        int csize = min(TILE, jmax - c0);
        // stage chunk: {pos, qc} -> float4
        for (int a = t; a < csize; a += 256) {
            int ja = c0 + a;
            sqp[a] = make_float4(pos[3 * ja], pos[3 * ja + 1], pos[3 * ja + 2],
                                 d_qraw[ja] - smeanv[batch[ja]]);
        }
        __syncthreads();

        if (active) {
            int lo = max(gs, c0) - c0;
            int hi = min(ge, c0 + csize) - c0;
            if (lo < hi) {
                int llast = hi - 1;
                for (int j0 = lo + lane; j0 < hi; j0 += 128) {
                    int j1 = j0 + 32, j2 = j0 + 64, j3 = j0 + 96;
                    float4 p0 = sqp[min(j0, llast)];
                    float4 p1 = sqp[min(j1, llast)];
                    float4 p2 = sqp[min(j2, llast)];
                    float4 p3 = sqp[min(j3, llast)];
                    float k0, k1, k2, k3;
                    float q0 = pair_term(p0, pi, soft2, nl, k0);
                    float q1 = pair_term(p1, pi, soft2, nl, k1);
                    float q2 = pair_term(p2, pi, soft2, nl, k2);
                    float q3 = pair_term(p3, pi, soft2, nl, k3);
                    acc = fmaf(q0, k0, acc);          // j0 < hi by loop condition
                    if (j1 < hi) acc = fmaf(q1, k1, acc);
                    if (j2 < hi) acc = fmaf(q2, k2, acc);
                    if (j3 < hi) acc = fmaf(q3, k3, acc);
                }
            }
        }
        __syncthreads();
    }

    // subtract self-term computed with the same intrinsic sequence
    if (active && lane == 0) {
        float ks;
        float qs = pair_term(pi, pi, soft2, nl, ks);
        acc -= qs * ks;
    }

#pragma unroll
    for (int off = 16; off; off >>= 1)
        acc += __shfl_down_sync(0xffffffffu, acc, off);

    if (active && lane == 0) out[i] = 0.5f * pi.w * acc;
}

// ---------------------------------------------------------------------------
// launch
// inputs: 0:x 1:pos 2:cell 3:W1 4:b1 5:W2 6:b2 7:screening 8:softening 9:batch
// ---------------------------------------------------------------------------
extern "C" void kernel_launch(void* const* d_in, const int* in_sizes, int n_in,
                              void* d_out, int out_size) {
    const float* x     = (const float*)d_in[0];
    const float* pos   = (const float*)d_in[1];
    const float* W1    = (const float*)d_in[3];
    const float* b1    = (const float*)d_in[4];
    const float* W2    = (const float*)d_in[5];
    const float* b2    = (const float*)d_in[6];
    const float* scr   = (const float*)d_in[7];
    const float* soft  = (const float*)d_in[8];
    const int*   batch = (const int*)d_in[9];
    float* out = (float*)d_out;

    int n = in_sizes[9];           // N atoms

    mlp_kernel<<<(n + 63) / 64, 256>>>(x, W1, b1, W2, b2, batch, n);
    pair_kernel<<<(n + 7) / 8, 256>>>(pos, batch, scr, soft, out, n);
}

// round 10
// speedup vs baseline: 1.5747x; 1.5747x over previous
#include <cuda_runtime.h>

// Problem constants (LatentCoulombLongRange: N=8192, F=128, H=64, B=8)
#define MAXN 8192
#define FDIM 128
#define HDIM 64
#define MAXB 64
#define NSLOT 32          // charge-sum slots per graph (atomic de-serialization)

// Scratch (allocation-free rule: __device__ globals; zero-initialized at load)
__device__ float  d_qraw[MAXN];
__device__ float4 d_qpos[MAXN];            // {x, y, z, centered q}
__device__ int    d_gstart[MAXB];
__device__ int    d_gend[MAXB];
__device__ float  d_gsum[MAXB * NSLOT];    // slotted per-graph q sums; re-zeroed by pair_kernel

// ---- raw single-MUFU intrinsics (avoid non-fast-math slow paths) ----------
__device__ __forceinline__ float fast_rsqrt(float x) {
    float r; asm("rsqrt.approx.ftz.f32 %0, %1;" : "=f"(r) : "f"(x)); return r;
}
__device__ __forceinline__ float fast_ex2(float x) {
    float r; asm("ex2.approx.ftz.f32 %0, %1;" : "=f"(r) : "f"(x)); return r;
}
__device__ __forceinline__ float fast_rcp(float x) {
    float r; asm("rcp.approx.ftz.f32 %0, %1;" : "=f"(r) : "f"(x)); return r;
}

#define LOG2E 1.44269504088896f

__device__ __forceinline__ float silu_f(float v) {
    return v * fast_rcp(1.0f + fast_ex2(-LOG2E * v));
}

// ---------------------------------------------------------------------------
// K1: charge-head MLP as a register-tiled GEMM (validated in R9: ~3-4us).
//     Block = 256 threads, tile = 64 atoms x 64 h, K=128 in 2 chunks of 64.
//     Thread (tx, ty) owns a 4x4 output tile; per k-step 2x LDS.128 -> 16 FFMA.
//     Epilogue: SiLU + W2 dot, reduce over tx via shfl_xor, then slotted
//     per-graph charge-sum atomics + sorted-batch boundary detection.
// ---------------------------------------------------------------------------
__global__ __launch_bounds__(256)
void mlp_kernel(const float* __restrict__ x,
                const float* __restrict__ W1,
                const float* __restrict__ b1,
                const float* __restrict__ W2,
                const float* __restrict__ b2,
                const int* __restrict__ batch,
                int n) {
    __shared__ float xs[64][68];   // [k_local][atom], padded rows
    __shared__ float ws[64][64];   // [k_local][h]

    int t  = threadIdx.x;
    int tx = t & 15, ty = t >> 4;
    int base = blockIdx.x * 64;
    int m0 = ty * 4, h0 = tx * 4;

    float acc[4][4] = {{0.f,0.f,0.f,0.f},{0.f,0.f,0.f,0.f},
                       {0.f,0.f,0.f,0.f},{0.f,0.f,0.f,0.f}};

    const float4* xv4  = (const float4*)x;    // 32 float4 per atom row
    const float4* w1v4 = (const float4*)W1;   // 16 float4 per f row

    for (int kc = 0; kc < FDIM; kc += 64) {
        // stage x chunk transposed: atoms base..base+63, f in [kc, kc+64)
        {
            int a  = t >> 2;                   // 0..63
            int u0 = t & 3;
            int arow = min(base + a, n - 1);
#pragma unroll
            for (int it = 0; it < 4; it++) {
                int u = u0 + it * 4;           // float4 unit within chunk
                float4 v = xv4[arow * (FDIM / 4) + (kc >> 2) + u];
                xs[4 * u + 0][a] = v.x;
                xs[4 * u + 1][a] = v.y;
                xs[4 * u + 2][a] = v.z;
                xs[4 * u + 3][a] = v.w;
            }
        }
        // stage W1 chunk: rows kc..kc+63
        {
#pragma unroll
            for (int it = 0; it < 4; it++) {
                int idx = t + it * 256;        // 0..1023
                int kl = idx >> 4, c4 = idx & 15;
                *(float4*)&ws[kl][c4 * 4] = w1v4[(kc + kl) * (HDIM / 4) + c4];
            }
        }
        __syncthreads();

#pragma unroll 8
        for (int k = 0; k < 64; k++) {
            float4 xf = *(const float4*)&xs[k][m0];
            float4 wf = *(const float4*)&ws[k][h0];
            acc[0][0] = fmaf(xf.x, wf.x, acc[0][0]);
            acc[0][1] = fmaf(xf.x, wf.y, acc[0][1]);
            acc[0][2] = fmaf(xf.x, wf.z, acc[0][2]);
            acc[0][3] = fmaf(xf.x, wf.w, acc[0][3]);
            acc[1][0] = fmaf(xf.y, wf.x, acc[1][0]);
            acc[1][1] = fmaf(xf.y, wf.y, acc[1][1]);
            acc[1][2] = fmaf(xf.y, wf.z, acc[1][2]);
            acc[1][3] = fmaf(xf.y, wf.w, acc[1][3]);
            acc[2][0] = fmaf(xf.z, wf.x, acc[2][0]);
            acc[2][1] = fmaf(xf.z, wf.y, acc[2][1]);
            acc[2][2] = fmaf(xf.z, wf.z, acc[2][2]);
            acc[2][3] = fmaf(xf.z, wf.w, acc[2][3]);
            acc[3][0] = fmaf(xf.w, wf.x, acc[3][0]);
            acc[3][1] = fmaf(xf.w, wf.y, acc[3][1]);
            acc[3][2] = fmaf(xf.w, wf.z, acc[3][2]);
            acc[3][3] = fmaf(xf.w, wf.w, acc[3][3]);
        }
        __syncthreads();
    }

    // epilogue: SiLU + W2 contraction over this thread's 4 h-cols
    float4 b1v = ((const float4*)b1)[tx];
    float4 w2v = ((const float4*)W2)[tx];
    float part[4];
#pragma unroll
    for (int a = 0; a < 4; a++) {
        float p;
        p = silu_f(acc[a][0] + b1v.x) * w2v.x;
        p = fmaf(silu_f(acc[a][1] + b1v.y), w2v.y, p);
        p = fmaf(silu_f(acc[a][2] + b1v.z), w2v.z, p);
        p = fmaf(silu_f(acc[a][3] + b1v.w), w2v.w, p);
        part[a] = p;
    }
#pragma unroll
    for (int off = 1; off < 16; off <<= 1) {
#pragma unroll
        for (int a = 0; a < 4; a++)
            part[a] += __shfl_xor_sync(0xffffffffu, part[a], off);
    }

    if (tx == 0) {
        float bias = b2[0];
#pragma unroll
        for (int a = 0; a < 4; a++) {
            int i = base + m0 + a;
            if (i < n) {
                float qi = part[a] + bias;
                d_qraw[i] = qi;
                int g = batch[i];
                atomicAdd(&d_gsum[g * NSLOT + (i & (NSLOT - 1))], qi);
                // sorted-batch segment boundaries
                if (i == 0     || batch[i - 1] != g) d_gstart[g] = i;
                if (i == n - 1 || batch[i + 1] != g) d_gend[g]   = i + 1;
            }
        }
    }
}

// ---------------------------------------------------------------------------
// K2: pack {pos, centered q} into float4. Per-graph mean reduced from the
//     slotted sums into SMEM at block start.
// ---------------------------------------------------------------------------
__global__ void pack_kernel(const float* __restrict__ pos,
                            const int* __restrict__ batch, int n, int nb) {
    __shared__ float smean[MAXB];
    int t = threadIdx.x;                   // 256 threads
    if (t < MAXB) smean[t] = 0.0f;
    __syncthreads();
    for (int s = t; s < nb * NSLOT; s += 256)
        atomicAdd(&smean[s / NSLOT], d_gsum[s]);
    __syncthreads();

    int i = blockIdx.x * 256 + t;
    if (i < n) {
        int g = batch[i];
        float cnt  = (float)max(1, d_gend[g] - d_gstart[g]);
        float mean = smean[g] / cnt;
        float qc = d_qraw[i] - mean;
        d_qpos[i] = make_float4(pos[3 * i], pos[3 * i + 1], pos[3 * i + 2], qc);
    }
}

// ---------------------------------------------------------------------------
// K3: screened Coulomb pair sum (best-known R8 version). One warp per atom;
//     lanes stride the atom's contiguous graph range, unrolled x4 for 4
//     independent MUFU chains (raw RSQ/EX2). Self-term included and then
//     subtracted with the IDENTICAL sequence so approximation error cancels.
//     Tail duty: block 0 re-zeroes d_gsum for the next graph replay.
// ---------------------------------------------------------------------------
__device__ __forceinline__ float pair_term(float4 pj, float4 pi,
                                           float soft2, float nscr_log2e,
                                           float& k_out) {
    float dx = pj.x - pi.x;
    float dy = pj.y - pi.y;
    float dz = pj.z - pi.z;
    float r2 = fmaf(dx, dx, fmaf(dy, dy, fmaf(dz, dz, soft2)));
    float rinv = fast_rsqrt(r2);
    float r = r2 * rinv;
    k_out = fast_ex2(nscr_log2e * r) * rinv;
    return pj.w;
}

__global__ void pair_kernel(const int* __restrict__ batch,
                            const float* __restrict__ scr_p,
                            const float* __restrict__ soft_p,
                            float* __restrict__ out, int n) {
    // reset slotted accumulators for the next replay (values already consumed)
    if (blockIdx.x == 0) {
#pragma unroll
        for (int s = threadIdx.x; s < MAXB * NSLOT; s += 256)
            d_gsum[s] = 0.0f;
    }

    int i    = (blockIdx.x * blockDim.x + threadIdx.x) >> 5;
    int lane = threadIdx.x & 31;
    if (i >= n) return;

    const float4* __restrict__ qp = d_qpos;

    float scr   = *scr_p;
    float soft  = *soft_p;
    float soft2 = soft * soft;
    const float nscr_log2e = -scr * LOG2E;

    int g  = batch[i];
    int gs = d_gstart[g];
    int ge = d_gend[g];

    float4 pi = qp[i];
    float acc = 0.0f;

    int jlast = ge - 1;
    for (int j0 = gs + lane; j0 < ge; j0 += 128) {
        int j1 = j0 + 32, j2 = j0 + 64, j3 = j0 + 96;
        float4 p0 = qp[min(j0, jlast)];
        float4 p1 = qp[min(j1, jlast)];
        float4 p2 = qp[min(j2, jlast)];
        float4 p3 = qp[min(j3, jlast)];
        float k0, k1, k2, k3;
        float q0 = pair_term(p0, pi, soft2, nscr_log2e, k0);
        float q1 = pair_term(p1, pi, soft2, nscr_log2e, k1);
        float q2 = pair_term(p2, pi, soft2, nscr_log2e, k2);
        float q3 = pair_term(p3, pi, soft2, nscr_log2e, k3);
        acc = fmaf(q0, k0, acc);                 // j0 < ge by loop condition
        if (j1 < ge) acc = fmaf(q1, k1, acc);
        if (j2 < ge) acc = fmaf(q2, k2, acc);
        if (j3 < ge) acc = fmaf(q3, k3, acc);
    }

    // subtract self-term computed with the same intrinsic sequence
    if (lane == 0) {
        float ks;
        float qs = pair_term(pi, pi, soft2, nscr_log2e, ks);
        acc -= qs * ks;
    }

#pragma unroll
    for (int off = 16; off; off >>= 1)
        acc += __shfl_down_sync(0xffffffffu, acc, off);

    if (lane == 0) out[i] = 0.5f * pi.w * acc;
}

// ---------------------------------------------------------------------------
// launch
// inputs: 0:x 1:pos 2:cell 3:W1 4:b1 5:W2 6:b2 7:screening 8:softening 9:batch
// ---------------------------------------------------------------------------
extern "C" void kernel_launch(void* const* d_in, const int* in_sizes, int n_in,
                              void* d_out, int out_size) {
    const float* x     = (const float*)d_in[0];
    const float* pos   = (const float*)d_in[1];
    const float* W1    = (const float*)d_in[3];
    const float* b1    = (const float*)d_in[4];
    const float* W2    = (const float*)d_in[5];
    const float* b2    = (const float*)d_in[6];
    const float* scr   = (const float*)d_in[7];
    const float* soft  = (const float*)d_in[8];
    const int*   batch = (const int*)d_in[9];
    float* out = (float*)d_out;

    int n  = in_sizes[9];          // N atoms
    int nb = in_sizes[2] / 9;      // B graphs (cell is [B,3,3])
    if (nb > MAXB) nb = MAXB;

    mlp_kernel<<<(n + 63) / 64, 256>>>(x, W1, b1, W2, b2, batch, n);
    pack_kernel<<<(n + 255) / 256, 256>>>(pos, batch, n, nb);
    int threads = 256;
    int blocks  = (n * 32 + threads - 1) / threads;
    pair_kernel<<<blocks, threads>>>(batch, scr, soft, out, n);
}